// round 1
// baseline (speedup 1.0000x reference)
#include <cuda_runtime.h>

// Scratch: partial batch-sums of x. [2 z-chunks][8 i][1152 c]
__device__ float g_xs_part[2 * 8 * 1152];

// Kernel A: xs_part[z][i][c] = sum_{b in chunk z} x[b, i, c]
// x layout: [B=256, I=8, C=1152] row-major.
__global__ void __launch_bounds__(128) reduce_x_kernel(const float* __restrict__ x) {
    const int c = blockIdx.x * 128 + threadIdx.x;   // 9 * 128 = 1152
    const int i = blockIdx.y;                        // 8
    const int z = blockIdx.z;                        // 2 chunks of 128 batches
    const float* p = x + (size_t)(z * 128) * 9216 + i * 1152 + c;
    float acc = 0.0f;
    #pragma unroll 8
    for (int b = 0; b < 128; ++b) {
        acc += p[(size_t)b * 9216];
    }
    g_xs_part[(z * 8 + i) * 1152 + c] = acc;
}

// Kernel B: per capsule c, compute u_sum[u][s] = sum_i W[c,u,s,i] * xs[i][c],
// then run 3 dynamic-routing iterations entirely in-block, write v[c,u,s].
// blockDim = 160 (one thread per (u,s) pair; U=10, S=16).
__global__ void __launch_bounds__(160) routing_kernel(const float* __restrict__ W,
                                                      float* __restrict__ out) {
    const int c = blockIdx.x;          // 1152
    const int t = threadIdx.x;         // 0..159
    const int u = t >> 4;
    const int s = t & 15;

    __shared__ float xsl[8];
    __shared__ float bl[10];    // routing logits b_ij
    __shared__ float red[10];   // per-u agreement scratch

    if (t < 8)  xsl[t] = g_xs_part[t * 1152 + c] + g_xs_part[(8 + t) * 1152 + c];
    if (t < 10) bl[t] = 0.0f;
    __syncthreads();

    // u_sum for this (u,s): dot of 8 weights with xs[i]
    const float4* wp = reinterpret_cast<const float4*>(
        W + ((((size_t)c * 10 + u) * 16 + s) * 8));
    const float4 w0 = __ldg(wp);
    const float4 w1 = __ldg(wp + 1);
    const float us = w0.x * xsl[0] + w0.y * xsl[1] + w0.z * xsl[2] + w0.w * xsl[3]
                   + w1.x * xsl[4] + w1.y * xsl[5] + w1.z * xsl[6] + w1.w * xsl[7];

    float v = 0.0f;
    #pragma unroll
    for (int it = 0; it < 3; ++it) {
        // softmax over u (10 values) — computed redundantly per thread from smem
        float m = bl[0];
        #pragma unroll
        for (int k = 1; k < 10; ++k) m = fmaxf(m, bl[k]);
        float denom = 0.0f;
        #pragma unroll
        for (int k = 0; k < 10; ++k) denom += expf(bl[k] - m);
        const float cij = expf(bl[u] - m) / denom;

        const float sj = cij * us;

        // ||s_j||^2 over the 16 s-lanes (stays within half-warp groups)
        float msq = sj * sj;
        #pragma unroll
        for (int off = 8; off > 0; off >>= 1)
            msq += __shfl_xor_sync(0xffffffffu, msq, off);

        // squash: v = msq/(1+msq) * sj/|s_j|
        v = (msq / (1.0f + msq)) * sj * rsqrtf(msq);

        if (it < 2) {
            // agreement: (sum_s u_sum * v) / B   (batch sum already folded into us)
            float a = us * v;
            #pragma unroll
            for (int off = 8; off > 0; off >>= 1)
                a += __shfl_xor_sync(0xffffffffu, a, off);
            if (s == 0) red[u] = a * (1.0f / 256.0f);
            __syncthreads();
            if (t < 10) bl[t] += red[t];
            __syncthreads();
        }
    }

    out[(size_t)c * 160 + t] = v;
}

extern "C" void kernel_launch(void* const* d_in, const int* in_sizes, int n_in,
                              void* d_out, int out_size) {
    const float* x = (const float*)d_in[0];   // [256, 8, 1152]
    const float* W = (const float*)d_in[1];   // [1, 1152, 10, 16, 8]
    float* out = (float*)d_out;               // [1152, 10, 16]

    reduce_x_kernel<<<dim3(9, 8, 2), 128>>>(x);
    routing_kernel<<<1152, 160>>>(W, out);
}

// round 2
// speedup vs baseline: 1.3690x; 1.3690x over previous
#include <cuda_runtime.h>

#define Z 16  // batch chunks

// Partial batch sums of x: [z][i][c] as floats = [16][8][1152]  (590 KB)
__device__ float g_part[Z * 8 * 1152];

// Kernel A: g_part[z][i][c] = sum over 16 batches of chunk z of x[b,i,c].
// x: [256, 8, 1152] f32 -> viewed as [256, 2304] float4 rows.
__global__ void __launch_bounds__(256) reduce_x_kernel(const float* __restrict__ x) {
    const int col = blockIdx.x * 256 + threadIdx.x;  // 0..2303 (float4 columns)
    const int z = blockIdx.y;                        // 0..15
    const float4* p = reinterpret_cast<const float4*>(x) + (size_t)z * 16 * 2304 + col;
    float4 a = make_float4(0.f, 0.f, 0.f, 0.f);
    #pragma unroll
    for (int b = 0; b < 16; ++b) {
        const float4 v = p[(size_t)b * 2304];
        a.x += v.x; a.y += v.y; a.z += v.z; a.w += v.w;
    }
    reinterpret_cast<float4*>(g_part)[(size_t)z * 2304 + col] = a;
}

// Kernel B: one WARP per capsule c. Lane owns 5 (u,s) pairs: t = k*32+lane,
// u = 2k + (lane>>4), s = lane&15. All routing math in registers + shuffles.
// No __syncthreads, no shared memory.
__global__ void __launch_bounds__(256) routing_kernel(const float* __restrict__ W,
                                                      float* __restrict__ out) {
    const int warp = threadIdx.x >> 5;
    const int lane = threadIdx.x & 31;
    const int c = blockIdx.x * 8 + warp;      // 144 blocks * 8 warps = 1152
    const int h = lane >> 4;                  // parity of u

    // xs[i][c]: lanes 0..7 sum the 16 partials for i = lane
    float xs_own = 0.f;
    if (lane < 8) {
        #pragma unroll
        for (int z = 0; z < Z; ++z)
            xs_own += g_part[(z * 8 + lane) * 1152 + c];
    }

    // W rows for this lane's 5 (u,s) pairs: 8 floats each = 2 float4
    float4 w0[5], w1[5];
    const float4* wp = reinterpret_cast<const float4*>(W + (size_t)c * 1280);
    #pragma unroll
    for (int k = 0; k < 5; ++k) {
        const int t = k * 32 + lane;
        w0[k] = __ldg(wp + 2 * t);
        w1[k] = __ldg(wp + 2 * t + 1);
    }

    // broadcast xs to all lanes
    float xsl[8];
    #pragma unroll
    for (int i = 0; i < 8; ++i) xsl[i] = __shfl_sync(0xffffffffu, xs_own, i);

    // u_sum (batch-summed u_hat) for each owned (u,s)
    float us[5];
    #pragma unroll
    for (int k = 0; k < 5; ++k) {
        us[k] = w0[k].x * xsl[0] + w0[k].y * xsl[1] + w0[k].z * xsl[2] + w0[k].w * xsl[3]
              + w1[k].x * xsl[4] + w1[k].y * xsl[5] + w1[k].z * xsl[6] + w1[k].w * xsl[7];
    }

    // routing logits, split by u parity so arrays stay in registers
    float be[5] = {0.f, 0.f, 0.f, 0.f, 0.f};  // u = 2k
    float bo[5] = {0.f, 0.f, 0.f, 0.f, 0.f};  // u = 2k+1
    float v[5];

    #pragma unroll
    for (int it = 0; it < 3; ++it) {
        // softmax over the 10 u's (each lane holds the full logit set)
        float m = be[0];
        #pragma unroll
        for (int k = 0; k < 5; ++k) { m = fmaxf(m, be[k]); m = fmaxf(m, bo[k]); }
        float ee[5], eo[5], denom = 0.f;
        #pragma unroll
        for (int k = 0; k < 5; ++k) {
            ee[k] = __expf(be[k] - m);
            eo[k] = __expf(bo[k] - m);
            denom += ee[k] + eo[k];
        }
        const float inv = 1.0f / denom;

        #pragma unroll
        for (int k = 0; k < 5; ++k) {
            const float cij = (h ? eo[k] : ee[k]) * inv;
            const float sj = cij * us[k];

            // ||s_j||^2 over the 16 s-lanes (xor<16 stays inside the half)
            float msq = sj * sj;
            #pragma unroll
            for (int off = 8; off; off >>= 1)
                msq += __shfl_xor_sync(0xffffffffu, msq, off);

            v[k] = msq / (1.0f + msq) * sj * rsqrtf(msq);

            if (it < 2) {
                // agreement: sum_s u_sum * v / B
                float a = us[k] * v[k];
                #pragma unroll
                for (int off = 8; off; off >>= 1)
                    a += __shfl_xor_sync(0xffffffffu, a, off);
                a *= (1.0f / 256.0f);
                const float ap = __shfl_xor_sync(0xffffffffu, a, 16);  // other parity
                be[k] += h ? ap : a;
                bo[k] += h ? a : ap;
            }
        }
    }

    // out[c, u, s] = v : index c*160 + t, coalesced per k
    #pragma unroll
    for (int k = 0; k < 5; ++k)
        out[(size_t)c * 160 + k * 32 + lane] = v[k];
}

extern "C" void kernel_launch(void* const* d_in, const int* in_sizes, int n_in,
                              void* d_out, int out_size) {
    const float* x = (const float*)d_in[0];   // [256, 8, 1152]
    const float* W = (const float*)d_in[1];   // [1, 1152, 10, 16, 8]
    float* out = (float*)d_out;               // [1152, 10, 16]

    reduce_x_kernel<<<dim3(9, Z), 256>>>(x);
    routing_kernel<<<144, 256>>>(W, out);
}